// round 13
// baseline (speedup 1.0000x reference)
#include <cuda_runtime.h>
#include <cuda_bf16.h>
#include <math.h>
#include <stdint.h>

#define EDIM 256
#define HIDDIM 1024
#define MROWS 32768          // B*N
#define DHEAD 1024           // tokens per (b,h) chunk
#define NBH 32

typedef __nv_bfloat16 bf16;

// ---------------- scratch (device globals; no allocations) ----------------
__device__ __align__(256) bf16  g_xn [MROWS * EDIM];
__device__ __align__(256) bf16  g_qkv[MROWS * 3 * EDIM];   // [row][768]: q|k|v
__device__ __align__(256) bf16  g_ob [MROWS * EDIM];
__device__ __align__(256) float g_x1 [MROWS * EDIM];
__device__ __align__(256) bf16  g_hb [MROWS * HIDDIM];
__device__ __align__(256) bf16  g_wqkv[3 * EDIM * EDIM];
__device__ __align__(256) bf16  g_wp [EDIM * EDIM];
__device__ __align__(256) bf16  g_w1 [HIDDIM * EDIM];
__device__ __align__(256) bf16  g_w2 [EDIM * HIDDIM];
__device__ __align__(256) float g_bqkv[3 * EDIM];

// ---------------- helpers ----------------
__device__ __forceinline__ uint32_t smem_u32(const void* p) {
    return (uint32_t)__cvta_generic_to_shared(p);
}
__device__ __forceinline__ void cp16(uint32_t s, const void* g) {
    asm volatile("cp.async.cg.shared.global [%0], [%1], 16;\n" :: "r"(s), "l"(g));
}
__device__ __forceinline__ void cp_commit() { asm volatile("cp.async.commit_group;\n"); }
__device__ __forceinline__ void cp_wait0()  { asm volatile("cp.async.wait_group 0;\n"); }

__device__ __forceinline__ void ldmA(uint32_t* a, uint32_t addr) {
    asm volatile("ldmatrix.sync.aligned.m8n8.x4.shared.b16 {%0,%1,%2,%3}, [%4];"
                 : "=r"(a[0]), "=r"(a[1]), "=r"(a[2]), "=r"(a[3]) : "r"(addr));
}
__device__ __forceinline__ void ldmB4(uint32_t* b, uint32_t addr) {
    asm volatile("ldmatrix.sync.aligned.m8n8.x4.shared.b16 {%0,%1,%2,%3}, [%4];"
                 : "=r"(b[0]), "=r"(b[1]), "=r"(b[2]), "=r"(b[3]) : "r"(addr));
}
__device__ __forceinline__ void ldmBT4(uint32_t* b, uint32_t addr) {
    asm volatile("ldmatrix.sync.aligned.m8n8.x4.trans.shared.b16 {%0,%1,%2,%3}, [%4];"
                 : "=r"(b[0]), "=r"(b[1]), "=r"(b[2]), "=r"(b[3]) : "r"(addr));
}
__device__ __forceinline__ void mma16816(float* c, const uint32_t* a, const uint32_t* b) {
    asm volatile("mma.sync.aligned.m16n8k16.row.col.f32.bf16.bf16.f32 "
                 "{%0,%1,%2,%3},{%4,%5,%6,%7},{%8,%9},{%0,%1,%2,%3};"
                 : "+f"(c[0]), "+f"(c[1]), "+f"(c[2]), "+f"(c[3])
                 : "r"(a[0]), "r"(a[1]), "r"(a[2]), "r"(a[3]), "r"(b[0]), "r"(b[1]));
}
__device__ __forceinline__ float mish_f(float x) {
    float sp = (x > 20.0f) ? x : __logf(1.0f + __expf(x));
    float t;
    asm("tanh.approx.f32 %0, %1;" : "=f"(t) : "f"(sp));
    return x * t;
}
__device__ __forceinline__ uint32_t packbf(float a, float b) {
    __nv_bfloat162 h = __floats2bfloat162_rn(a, b);
    return *(uint32_t*)&h;
}

// ---------------- weights fp32->bf16 + bias concat, ONE launch ----------------
__global__ void cvt_all(const float* __restrict__ Wq, const float* __restrict__ Wk,
                        const float* __restrict__ Wv, const float* __restrict__ Wp,
                        const float* __restrict__ W1, const float* __restrict__ W2,
                        const float* __restrict__ bq, const float* __restrict__ bk,
                        const float* __restrict__ bv) {
    int i = blockIdx.x * 256 + threadIdx.x;
    if (i < 65536)        g_wqkv[i] = __float2bfloat16(Wq[i]);
    else if (i < 131072)  g_wqkv[i] = __float2bfloat16(Wk[i - 65536]);
    else if (i < 196608)  g_wqkv[i] = __float2bfloat16(Wv[i - 131072]);
    else if (i < 262144)  g_wp[i - 196608] = __float2bfloat16(Wp[i - 196608]);
    else if (i < 524288)  g_w1[i - 262144] = __float2bfloat16(W1[i - 262144]);
    else if (i < 786432)  g_w2[i - 524288] = __float2bfloat16(W2[i - 524288]);
    else {
        int j = i - 786432;   // 0..767
        if (j < 768)
            g_bqkv[j] = (j < 256) ? bq[j] : (j < 512 ? bk[j - 256] : bv[j - 512]);
    }
}

// ---------------- LayerNorm (fp32 in -> bf16 out) ----------------
__global__ __launch_bounds__(256) void ln_kernel(const float* __restrict__ x,
                                                 const float* __restrict__ w,
                                                 const float* __restrict__ b,
                                                 bf16* __restrict__ y) {
    int warp = threadIdx.x >> 5, lane = threadIdx.x & 31;
    int row = blockIdx.x * 8 + warp;
    const float* xr = x + (size_t)row * EDIM;
    float v[8];
#pragma unroll
    for (int i = 0; i < 8; i++) v[i] = xr[lane + i * 32];
    float s = 0.f;
#pragma unroll
    for (int i = 0; i < 8; i++) s += v[i];
#pragma unroll
    for (int o = 16; o > 0; o >>= 1) s += __shfl_xor_sync(0xffffffffu, s, o);
    float mu = s * (1.f / 256.f);
    float vs = 0.f;
#pragma unroll
    for (int i = 0; i < 8; i++) { float d = v[i] - mu; vs += d * d; }
#pragma unroll
    for (int o = 16; o > 0; o >>= 1) vs += __shfl_xor_sync(0xffffffffu, vs, o);
    float inv = rsqrtf(vs * (1.f / 256.f) + 1e-5f);
    bf16* yr = y + (size_t)row * EDIM;
#pragma unroll
    for (int i = 0; i < 8; i++) {
        int c = lane + i * 32;
        yr[c] = __float2bfloat16((v[i] - mu) * inv * w[c] + b[c]);
    }
}

// ---------------- TN GEMM: C[M,N] = epi(A[M,K] @ B[N,K]^T + bias) ----------------
// CTA 128x128, 8 warps (2m x 4n), warp tile 64x32, BK=64, 2-stage cp.async (R9 best).
#define SKA 72
#define GSMEM (2 * 2 * 128 * SKA * 2)
template <int ACT, int RES, int OUTBF>
__global__ __launch_bounds__(256) void gemm_tn(const bf16* __restrict__ A,
                                               const bf16* __restrict__ B,
                                               const float* __restrict__ bias,
                                               const float* __restrict__ res,
                                               float* __restrict__ Cf,
                                               bf16* __restrict__ Cb,
                                               int M, int N, int K) {
    extern __shared__ bf16 gsm[];
    bf16* As = gsm;                     // [2][128*SKA]
    bf16* Bs = gsm + 2 * 128 * SKA;     // [2][128*SKA]
    int tid = threadIdx.x, lane = tid & 31, warp = tid >> 5;
    int wm = warp >> 2, wn = warp & 3;
    int m0 = blockIdx.y * 128, n0 = blockIdx.x * 128;
    uint32_t sA = smem_u32(As), sB = smem_u32(Bs);
    const uint32_t stageB = 128 * SKA * 2;

    float acc[4][4][4];
#pragma unroll
    for (int i = 0; i < 4; i++)
#pragma unroll
        for (int j = 0; j < 4; j++)
#pragma unroll
            for (int t = 0; t < 4; t++) acc[i][j][t] = 0.f;

    int KT = K >> 6;

    auto load = [&](int st, int kt) {
#pragma unroll
        for (int i = 0; i < 4; i++) {
            int id = i * 256 + tid, r = id >> 3, c = id & 7;
            cp16(sA + st * stageB + (r * SKA + c * 8) * 2,
                 A + (size_t)(m0 + r) * K + kt * 64 + c * 8);
            cp16(sB + st * stageB + (r * SKA + c * 8) * 2,
                 B + (size_t)(n0 + r) * K + kt * 64 + c * 8);
        }
    };

    load(0, 0); cp_commit(); cp_wait0(); __syncthreads();
    for (int kt = 0; kt < KT; kt++) {
        int st = kt & 1;
        if (kt + 1 < KT) { load(st ^ 1, kt + 1); cp_commit(); }
        uint32_t ba = sA + st * stageB;
        uint32_t bb = sB + st * stageB;
#pragma unroll
        for (int kk = 0; kk < 4; kk++) {
            uint32_t af[4][4], bfr[4][2];
#pragma unroll
            for (int mi = 0; mi < 4; mi++) {
                int row = wm * 64 + mi * 16 + (lane & 15);
                ldmA(af[mi], ba + (row * SKA + kk * 16 + (lane >> 4) * 8) * 2);
            }
#pragma unroll
            for (int nh = 0; nh < 2; nh++) {
                uint32_t bt[4];
                int nrow = wn * 32 + nh * 16 + (lane >> 4) * 8 + (lane & 7);
                ldmB4(bt, bb + (nrow * SKA + kk * 16 + ((lane >> 3) & 1) * 8) * 2);
                bfr[nh * 2][0] = bt[0]; bfr[nh * 2][1] = bt[1];
                bfr[nh * 2 + 1][0] = bt[2]; bfr[nh * 2 + 1][1] = bt[3];
            }
#pragma unroll
            for (int mi = 0; mi < 4; mi++)
#pragma unroll
                for (int ni = 0; ni < 4; ni++) mma16816(acc[mi][ni], af[mi], bfr[ni]);
        }
        if (kt + 1 < KT) cp_wait0();
        __syncthreads();
    }

#pragma unroll
    for (int mi = 0; mi < 4; mi++) {
#pragma unroll
        for (int ni = 0; ni < 4; ni++) {
            int c0 = n0 + wn * 32 + ni * 8 + (lane & 3) * 2;
            float b0 = 0.f, b1 = 0.f;
            if (bias) { b0 = bias[c0]; b1 = bias[c0 + 1]; }
#pragma unroll
            for (int h = 0; h < 2; h++) {
                int r = m0 + wm * 64 + mi * 16 + (lane >> 2) + h * 8;
                float v0 = acc[mi][ni][h * 2 + 0] + b0;
                float v1 = acc[mi][ni][h * 2 + 1] + b1;
                if (ACT) { v0 = mish_f(v0); v1 = mish_f(v1); }
                if (RES) {
                    float2 rr = *(const float2*)(res + (size_t)r * N + c0);
                    v0 += rr.x; v1 += rr.y;
                }
                if (OUTBF)
                    *(__nv_bfloat162*)(Cb + (size_t)r * N + c0) = __floats2bfloat162_rn(v0, v1);
                else
                    *(float2*)(Cf + (size_t)r * N + c0) = make_float2(v0, v1);
            }
        }
    }
}

// ---------------- Fused flash attention: small-CTA for 2 CTAs/SM overlap --------
// Br=64, Bc=32, d=256. 128 threads (4 warps, 16 q-rows each).
// grid (32 bh, 16 qtiles). smem 101 KB -> 2 CTAs/SM; serial softmax of one CTA
// overlaps the other CTA's tensor work.
#define BR 64
#define BC 32
#define SKV 264
#define FSMEM ((BR * SKV + 4 * BC * SKV) * 2)   // Q + 2-stage K + 2-stage V

__global__ __launch_bounds__(128, 2) void flash_kernel(const bf16* __restrict__ qkv,
                                                       bf16* __restrict__ o) {
    extern __shared__ bf16 fsm[];
    bf16* Qs = fsm;                         // [BR][SKV]
    bf16* Ks = Qs + BR * SKV;               // [2][BC][SKV]
    bf16* Vs = Ks + 2 * BC * SKV;           // [2][BC][SKV]
    int tid = threadIdx.x, lane = tid & 31, warp = tid >> 5;
    int bh = blockIdx.x, qt = blockIdx.y;
    size_t tokBase = (size_t)bh * DHEAD;
    uint32_t sQ = smem_u32(Qs), sK = smem_u32(Ks), sV = smem_u32(Vs);
    const uint32_t stKV = BC * SKV * 2;

    // load Q (64 rows x 32 chunks = 2048 chunks, 16/thread)
    {
        const bf16* qg = qkv + (tokBase + (size_t)qt * BR) * 768;
#pragma unroll
        for (int i = 0; i < 16; i++) {
            int c = tid + i * 128; int r = c >> 5, c8 = c & 31;
            cp16(sQ + (r * SKV + c8 * 8) * 2, qg + (size_t)r * 768 + c8 * 8);
        }
    }
    auto loadKV = [&](int st, int kt) {
        const bf16* kg = qkv + (tokBase + (size_t)kt * BC) * 768 + 256;
#pragma unroll
        for (int i = 0; i < 8; i++) {
            int c = tid + i * 128; int r = c >> 5, c8 = c & 31;   // 32 rows x 32 chunks
            cp16(sK + st * stKV + (r * SKV + c8 * 8) * 2, kg + (size_t)r * 768 + c8 * 8);
            cp16(sV + st * stKV + (r * SKV + c8 * 8) * 2, kg + (size_t)r * 768 + 256 + c8 * 8);
        }
    };
    loadKV(0, 0); cp_commit(); cp_wait0(); __syncthreads();

    float oacc[32][4];
#pragma unroll
    for (int i = 0; i < 32; i++)
#pragma unroll
        for (int t = 0; t < 4; t++) oacc[i][t] = 0.f;
    float l0 = 0.f, l1 = 0.f;

    int qrow = warp * 16 + (lane & 15);

    for (int kt = 0; kt < DHEAD / BC; kt++) {      // 32 iterations
        int st = kt & 1;
        if (kt + 1 < DHEAD / BC) { loadKV(st ^ 1, kt + 1); cp_commit(); }

        // ---- S = Q @ K^T : warp computes 16x32 ----
        float sacc[4][4];
#pragma unroll
        for (int n = 0; n < 4; n++)
#pragma unroll
            for (int t = 0; t < 4; t++) sacc[n][t] = 0.f;
#pragma unroll
        for (int k2 = 0; k2 < 8; k2++) {
            uint32_t a0[4], a1[4];
            ldmA(a0, sQ + (qrow * SKV + k2 * 32 + (lane >> 4) * 8) * 2);
            ldmA(a1, sQ + (qrow * SKV + k2 * 32 + 16 + (lane >> 4) * 8) * 2);
#pragma unroll
            for (int n = 0; n < 4; n++) {
                uint32_t bb[4];
                ldmB4(bb, sK + st * stKV +
                          ((n * 8 + (lane & 7)) * SKV + k2 * 32 + ((lane >> 3) & 3) * 8) * 2);
                mma16816(sacc[n], a0, bb);
                mma16816(sacc[n], a1, bb + 2);
            }
        }

        // ---- exp (no max; scores bounded) + pack ----
        uint32_t pa[2][4];
#pragma unroll
        for (int j = 0; j < 2; j++) {
            float e00 = __expf(sacc[2 * j][0]), e01 = __expf(sacc[2 * j][1]);
            float e02 = __expf(sacc[2 * j][2]), e03 = __expf(sacc[2 * j][3]);
            float e10 = __expf(sacc[2 * j + 1][0]), e11 = __expf(sacc[2 * j + 1][1]);
            float e12 = __expf(sacc[2 * j + 1][2]), e13 = __expf(sacc[2 * j + 1][3]);
            l0 += e00 + e01 + e10 + e11;
            l1 += e02 + e03 + e12 + e13;
            pa[j][0] = packbf(e00, e01);
            pa[j][1] = packbf(e02, e03);
            pa[j][2] = packbf(e10, e11);
            pa[j][3] = packbf(e12, e13);
        }

        // ---- O += P @ V ----
#pragma unroll
        for (int j = 0; j < 2; j++) {
#pragma unroll
            for (int np = 0; np < 16; np++) {
                uint32_t bb[4];
                ldmBT4(bb, sV + st * stKV +
                           ((j * 16 + (lane & 15)) * SKV + np * 16 + ((lane >> 4) & 1) * 8) * 2);
                mma16816(oacc[2 * np], pa[j], bb);
                mma16816(oacc[2 * np + 1], pa[j], bb + 2);
            }
        }

        if (kt + 1 < DHEAD / BC) cp_wait0();
        __syncthreads();
    }

    l0 += __shfl_xor_sync(0xffffffffu, l0, 1);
    l0 += __shfl_xor_sync(0xffffffffu, l0, 2);
    l1 += __shfl_xor_sync(0xffffffffu, l1, 1);
    l1 += __shfl_xor_sync(0xffffffffu, l1, 2);
    float inv0 = 1.f / (l0 * 16.f), inv1 = 1.f / (l1 * 16.f);
    int row0 = (int)(tokBase) + qt * BR + warp * 16 + (lane >> 2);
#pragma unroll
    for (int c = 0; c < 32; c++) {
        int col = c * 8 + (lane & 3) * 2;
        *(__nv_bfloat162*)(o + (size_t)row0 * EDIM + col) =
            __floats2bfloat162_rn(oacc[c][0] * inv0, oacc[c][1] * inv0);
        *(__nv_bfloat162*)(o + (size_t)(row0 + 8) * EDIM + col) =
            __floats2bfloat162_rn(oacc[c][2] * inv1, oacc[c][3] * inv1);
    }
}

// ---------------- host launch ----------------
extern "C" void kernel_launch(void* const* d_in, const int* in_sizes, int n_in,
                              void* d_out, int out_size) {
    const float* x    = (const float*)d_in[0];
    const float* ln1w = (const float*)d_in[1];
    const float* ln1b = (const float*)d_in[2];
    const float* Wq   = (const float*)d_in[3];
    const float* bq   = (const float*)d_in[4];
    const float* Wk   = (const float*)d_in[5];
    const float* bk   = (const float*)d_in[6];
    const float* Wv   = (const float*)d_in[7];
    const float* bv   = (const float*)d_in[8];
    const float* Wp   = (const float*)d_in[9];
    const float* bp   = (const float*)d_in[10];
    const float* ln2w = (const float*)d_in[11];
    const float* ln2b = (const float*)d_in[12];
    const float* W1   = (const float*)d_in[13];
    const float* b1   = (const float*)d_in[14];
    const float* W2   = (const float*)d_in[15];
    const float* b2   = (const float*)d_in[16];
    float* out = (float*)d_out;

    bf16 *xn, *qkv, *ob, *hb, *wqkv, *wp, *w1, *w2;
    float *x1, *bqkv;
    cudaGetSymbolAddress((void**)&xn,   g_xn);
    cudaGetSymbolAddress((void**)&qkv,  g_qkv);
    cudaGetSymbolAddress((void**)&ob,   g_ob);
    cudaGetSymbolAddress((void**)&x1,   g_x1);
    cudaGetSymbolAddress((void**)&hb,   g_hb);
    cudaGetSymbolAddress((void**)&wqkv, g_wqkv);
    cudaGetSymbolAddress((void**)&wp,   g_wp);
    cudaGetSymbolAddress((void**)&w1,   g_w1);
    cudaGetSymbolAddress((void**)&w2,   g_w2);
    cudaGetSymbolAddress((void**)&bqkv, g_bqkv);

    cudaFuncSetAttribute(flash_kernel, cudaFuncAttributeMaxDynamicSharedMemorySize, FSMEM);
    cudaFuncSetAttribute(gemm_tn<0, 0, 1>, cudaFuncAttributeMaxDynamicSharedMemorySize, GSMEM);
    cudaFuncSetAttribute(gemm_tn<0, 1, 0>, cudaFuncAttributeMaxDynamicSharedMemorySize, GSMEM);
    cudaFuncSetAttribute(gemm_tn<1, 0, 1>, cudaFuncAttributeMaxDynamicSharedMemorySize, GSMEM);
    cudaFuncSetAttribute(gemm_tn<1, 1, 0>, cudaFuncAttributeMaxDynamicSharedMemorySize, GSMEM);

    cvt_all<<<3075, 256>>>(Wq, Wk, Wv, Wp, W1, W2, bq, bk, bv);
    ln_kernel<<<MROWS / 8, 256>>>(x, ln1w, ln1b, xn);
    // QKV: [M,768] = xn @ Wqkv^T + bqkv
    gemm_tn<0, 0, 1><<<dim3(6, 256), 256, GSMEM>>>(xn, wqkv, bqkv, nullptr, nullptr, qkv,
                                                   MROWS, 3 * EDIM, EDIM);
    flash_kernel<<<dim3(NBH, DHEAD / BR), 128, FSMEM>>>(qkv, ob);
    // x1 = O @ Wp^T + bp + x
    gemm_tn<0, 1, 0><<<dim3(2, 256), 256, GSMEM>>>(ob, wp, bp, x, x1, nullptr,
                                                   MROWS, EDIM, EDIM);
    ln_kernel<<<MROWS / 8, 256>>>(x1, ln2w, ln2b, xn);
    // h = mish(xn @ W1^T + b1)
    gemm_tn<1, 0, 1><<<dim3(8, 256), 256, GSMEM>>>(xn, w1, b1, nullptr, nullptr, hb,
                                                   MROWS, HIDDIM, EDIM);
    // out = mish(h @ W2^T + b2) + x1
    gemm_tn<1, 1, 0><<<dim3(2, 256), 256, GSMEM>>>(hb, w2, b2, x1, out, nullptr,
                                                   MROWS, EDIM, HIDDIM);
}

// round 14
// speedup vs baseline: 1.0361x; 1.0361x over previous
#include <cuda_runtime.h>
#include <cuda_bf16.h>
#include <math.h>
#include <stdint.h>

#define EDIM 256
#define HIDDIM 1024
#define MROWS 32768          // B*N
#define DHEAD 1024           // tokens per (b,h) chunk
#define NBH 32

typedef __nv_bfloat16 bf16;

// ---------------- scratch (device globals; no allocations) ----------------
__device__ __align__(256) bf16  g_xn [MROWS * EDIM];
__device__ __align__(256) bf16  g_qkv[MROWS * 3 * EDIM];   // [row][768]: q|k|v (q pre-scaled by log2e)
__device__ __align__(256) bf16  g_ob [MROWS * EDIM];
__device__ __align__(256) float g_x1 [MROWS * EDIM];
__device__ __align__(256) bf16  g_hb [MROWS * HIDDIM];
__device__ __align__(256) bf16  g_wqkv[3 * EDIM * EDIM];
__device__ __align__(256) bf16  g_wp [EDIM * EDIM];
__device__ __align__(256) bf16  g_w1 [HIDDIM * EDIM];
__device__ __align__(256) bf16  g_w2 [EDIM * HIDDIM];
__device__ __align__(256) float g_bqkv[3 * EDIM];

#define LOG2E 1.4426950408889634f

// ---------------- helpers ----------------
__device__ __forceinline__ uint32_t smem_u32(const void* p) {
    return (uint32_t)__cvta_generic_to_shared(p);
}
__device__ __forceinline__ void cp16(uint32_t s, const void* g) {
    asm volatile("cp.async.cg.shared.global [%0], [%1], 16;\n" :: "r"(s), "l"(g));
}
__device__ __forceinline__ void cp_commit() { asm volatile("cp.async.commit_group;\n"); }
__device__ __forceinline__ void cp_wait0()  { asm volatile("cp.async.wait_group 0;\n"); }

__device__ __forceinline__ void ldmA(uint32_t* a, uint32_t addr) {
    asm volatile("ldmatrix.sync.aligned.m8n8.x4.shared.b16 {%0,%1,%2,%3}, [%4];"
                 : "=r"(a[0]), "=r"(a[1]), "=r"(a[2]), "=r"(a[3]) : "r"(addr));
}
__device__ __forceinline__ void ldmB4(uint32_t* b, uint32_t addr) {
    asm volatile("ldmatrix.sync.aligned.m8n8.x4.shared.b16 {%0,%1,%2,%3}, [%4];"
                 : "=r"(b[0]), "=r"(b[1]), "=r"(b[2]), "=r"(b[3]) : "r"(addr));
}
__device__ __forceinline__ void ldmBT4(uint32_t* b, uint32_t addr) {
    asm volatile("ldmatrix.sync.aligned.m8n8.x4.trans.shared.b16 {%0,%1,%2,%3}, [%4];"
                 : "=r"(b[0]), "=r"(b[1]), "=r"(b[2]), "=r"(b[3]) : "r"(addr));
}
__device__ __forceinline__ void mma16816(float* c, const uint32_t* a, const uint32_t* b) {
    asm volatile("mma.sync.aligned.m16n8k16.row.col.f32.bf16.bf16.f32 "
                 "{%0,%1,%2,%3},{%4,%5,%6,%7},{%8,%9},{%0,%1,%2,%3};"
                 : "+f"(c[0]), "+f"(c[1]), "+f"(c[2]), "+f"(c[3])
                 : "r"(a[0]), "r"(a[1]), "r"(a[2]), "r"(a[3]), "r"(b[0]), "r"(b[1]));
}
__device__ __forceinline__ float mish_f(float x) {
    float sp = (x > 20.0f) ? x : __logf(1.0f + __expf(x));
    float t;
    asm("tanh.approx.f32 %0, %1;" : "=f"(t) : "f"(sp));
    return x * t;
}
__device__ __forceinline__ uint32_t packbf(float a, float b) {
    __nv_bfloat162 h = __floats2bfloat162_rn(a, b);
    return *(uint32_t*)&h;
}
__device__ __forceinline__ uint32_t ex2_bf16x2(uint32_t x) {
    uint32_t r;
    asm("ex2.approx.ftz.bf16x2 %0, %1;" : "=r"(r) : "r"(x));
    return r;
}

// ---------------- weights fp32->bf16 + bias concat, ONE launch ----------------
// Wq/bq pre-scaled by log2(e): S accumulates in log2 domain -> packed ex2.
__global__ void cvt_all(const float* __restrict__ Wq, const float* __restrict__ Wk,
                        const float* __restrict__ Wv, const float* __restrict__ Wp,
                        const float* __restrict__ W1, const float* __restrict__ W2,
                        const float* __restrict__ bq, const float* __restrict__ bk,
                        const float* __restrict__ bv) {
    int i = blockIdx.x * 256 + threadIdx.x;
    if (i < 65536)        g_wqkv[i] = __float2bfloat16(Wq[i] * LOG2E);
    else if (i < 131072)  g_wqkv[i] = __float2bfloat16(Wk[i - 65536]);
    else if (i < 196608)  g_wqkv[i] = __float2bfloat16(Wv[i - 131072]);
    else if (i < 262144)  g_wp[i - 196608] = __float2bfloat16(Wp[i - 196608]);
    else if (i < 524288)  g_w1[i - 262144] = __float2bfloat16(W1[i - 262144]);
    else if (i < 786432)  g_w2[i - 524288] = __float2bfloat16(W2[i - 524288]);
    else {
        int j = i - 786432;   // 0..767
        if (j < 768)
            g_bqkv[j] = (j < 256) ? bq[j] * LOG2E : (j < 512 ? bk[j - 256] : bv[j - 512]);
    }
}

// ---------------- LayerNorm (fp32 in -> bf16 out) ----------------
__global__ __launch_bounds__(256) void ln_kernel(const float* __restrict__ x,
                                                 const float* __restrict__ w,
                                                 const float* __restrict__ b,
                                                 bf16* __restrict__ y) {
    int warp = threadIdx.x >> 5, lane = threadIdx.x & 31;
    int row = blockIdx.x * 8 + warp;
    const float* xr = x + (size_t)row * EDIM;
    float v[8];
#pragma unroll
    for (int i = 0; i < 8; i++) v[i] = xr[lane + i * 32];
    float s = 0.f;
#pragma unroll
    for (int i = 0; i < 8; i++) s += v[i];
#pragma unroll
    for (int o = 16; o > 0; o >>= 1) s += __shfl_xor_sync(0xffffffffu, s, o);
    float mu = s * (1.f / 256.f);
    float vs = 0.f;
#pragma unroll
    for (int i = 0; i < 8; i++) { float d = v[i] - mu; vs += d * d; }
#pragma unroll
    for (int o = 16; o > 0; o >>= 1) vs += __shfl_xor_sync(0xffffffffu, vs, o);
    float inv = rsqrtf(vs * (1.f / 256.f) + 1e-5f);
    bf16* yr = y + (size_t)row * EDIM;
#pragma unroll
    for (int i = 0; i < 8; i++) {
        int c = lane + i * 32;
        yr[c] = __float2bfloat16((v[i] - mu) * inv * w[c] + b[c]);
    }
}

// ---------------- TN GEMM: C[M,N] = epi(A[M,K] @ B[N,K]^T + bias) ----------------
// CTA 128x128, 8 warps (2m x 4n), warp tile 64x32, BK=64, 2-stage cp.async (R9 best).
#define SKA 72
#define GSMEM (2 * 2 * 128 * SKA * 2)
template <int ACT, int RES, int OUTBF>
__global__ __launch_bounds__(256) void gemm_tn(const bf16* __restrict__ A,
                                               const bf16* __restrict__ B,
                                               const float* __restrict__ bias,
                                               const float* __restrict__ res,
                                               float* __restrict__ Cf,
                                               bf16* __restrict__ Cb,
                                               int M, int N, int K) {
    extern __shared__ bf16 gsm[];
    bf16* As = gsm;
    bf16* Bs = gsm + 2 * 128 * SKA;
    int tid = threadIdx.x, lane = tid & 31, warp = tid >> 5;
    int wm = warp >> 2, wn = warp & 3;
    int m0 = blockIdx.y * 128, n0 = blockIdx.x * 128;
    uint32_t sA = smem_u32(As), sB = smem_u32(Bs);
    const uint32_t stageB = 128 * SKA * 2;

    float acc[4][4][4];
#pragma unroll
    for (int i = 0; i < 4; i++)
#pragma unroll
        for (int j = 0; j < 4; j++)
#pragma unroll
            for (int t = 0; t < 4; t++) acc[i][j][t] = 0.f;

    int KT = K >> 6;

    auto load = [&](int st, int kt) {
#pragma unroll
        for (int i = 0; i < 4; i++) {
            int id = i * 256 + tid, r = id >> 3, c = id & 7;
            cp16(sA + st * stageB + (r * SKA + c * 8) * 2,
                 A + (size_t)(m0 + r) * K + kt * 64 + c * 8);
            cp16(sB + st * stageB + (r * SKA + c * 8) * 2,
                 B + (size_t)(n0 + r) * K + kt * 64 + c * 8);
        }
    };

    load(0, 0); cp_commit(); cp_wait0(); __syncthreads();
    for (int kt = 0; kt < KT; kt++) {
        int st = kt & 1;
        if (kt + 1 < KT) { load(st ^ 1, kt + 1); cp_commit(); }
        uint32_t ba = sA + st * stageB;
        uint32_t bb = sB + st * stageB;
#pragma unroll
        for (int kk = 0; kk < 4; kk++) {
            uint32_t af[4][4], bfr[4][2];
#pragma unroll
            for (int mi = 0; mi < 4; mi++) {
                int row = wm * 64 + mi * 16 + (lane & 15);
                ldmA(af[mi], ba + (row * SKA + kk * 16 + (lane >> 4) * 8) * 2);
            }
#pragma unroll
            for (int nh = 0; nh < 2; nh++) {
                uint32_t bt[4];
                int nrow = wn * 32 + nh * 16 + (lane >> 4) * 8 + (lane & 7);
                ldmB4(bt, bb + (nrow * SKA + kk * 16 + ((lane >> 3) & 1) * 8) * 2);
                bfr[nh * 2][0] = bt[0]; bfr[nh * 2][1] = bt[1];
                bfr[nh * 2 + 1][0] = bt[2]; bfr[nh * 2 + 1][1] = bt[3];
            }
#pragma unroll
            for (int mi = 0; mi < 4; mi++)
#pragma unroll
                for (int ni = 0; ni < 4; ni++) mma16816(acc[mi][ni], af[mi], bfr[ni]);
        }
        if (kt + 1 < KT) cp_wait0();
        __syncthreads();
    }

#pragma unroll
    for (int mi = 0; mi < 4; mi++) {
#pragma unroll
        for (int ni = 0; ni < 4; ni++) {
            int c0 = n0 + wn * 32 + ni * 8 + (lane & 3) * 2;
            float b0 = 0.f, b1 = 0.f;
            if (bias) { b0 = bias[c0]; b1 = bias[c0 + 1]; }
#pragma unroll
            for (int h = 0; h < 2; h++) {
                int r = m0 + wm * 64 + mi * 16 + (lane >> 2) + h * 8;
                float v0 = acc[mi][ni][h * 2 + 0] + b0;
                float v1 = acc[mi][ni][h * 2 + 1] + b1;
                if (ACT) { v0 = mish_f(v0); v1 = mish_f(v1); }
                if (RES) {
                    float2 rr = *(const float2*)(res + (size_t)r * N + c0);
                    v0 += rr.x; v1 += rr.y;
                }
                if (OUTBF)
                    *(__nv_bfloat162*)(Cb + (size_t)r * N + c0) = __floats2bfloat162_rn(v0, v1);
                else
                    *(float2*)(Cf + (size_t)r * N + c0) = make_float2(v0, v1);
            }
        }
    }
}

// ---------------- Fused flash attention (R9 skeleton + packed ex2 + l-via-MMA) ---
// grid (32 bh, 8 qtiles) x 256 threads. Br=128, Bc=64, d=256.
// S is accumulated in log2 domain (q pre-scaled); exp via ex2.bf16x2 on packed
// pairs; row sums l accumulated by 4 extra MMAs against an all-ones B fragment.
#define BR 128
#define BC 64
#define SKV 264
#define FSMEM ((BR * SKV + 4 * BC * SKV) * 2)

__global__ __launch_bounds__(256, 1) void flash_kernel(const bf16* __restrict__ qkv,
                                                       bf16* __restrict__ o) {
    extern __shared__ bf16 fsm[];
    bf16* Qs = fsm;
    bf16* Ks = Qs + BR * SKV;
    bf16* Vs = Ks + 2 * BC * SKV;
    int tid = threadIdx.x, lane = tid & 31, warp = tid >> 5;
    int bh = blockIdx.x, qt = blockIdx.y;
    size_t tokBase = (size_t)bh * DHEAD;
    uint32_t sQ = smem_u32(Qs), sK = smem_u32(Ks), sV = smem_u32(Vs);
    const uint32_t stKV = BC * SKV * 2;

    {
        const bf16* qg = qkv + (tokBase + (size_t)qt * BR) * 768;
#pragma unroll
        for (int i = 0; i < 16; i++) {
            int c = tid + i * 256; int r = c >> 5, c8 = c & 31;
            cp16(sQ + (r * SKV + c8 * 8) * 2, qg + (size_t)r * 768 + c8 * 8);
        }
    }
    auto loadKV = [&](int st, int kt) {
        const bf16* kg = qkv + (tokBase + (size_t)kt * BC) * 768 + 256;
#pragma unroll
        for (int i = 0; i < 8; i++) {
            int c = tid + i * 256; int r = c >> 5, c8 = c & 31;
            cp16(sK + st * stKV + (r * SKV + c8 * 8) * 2, kg + (size_t)r * 768 + c8 * 8);
            cp16(sV + st * stKV + (r * SKV + c8 * 8) * 2, kg + (size_t)r * 768 + 256 + c8 * 8);
        }
    };
    loadKV(0, 0); cp_commit(); cp_wait0(); __syncthreads();

    float oacc[32][4];
#pragma unroll
    for (int i = 0; i < 32; i++)
#pragma unroll
        for (int t = 0; t < 4; t++) oacc[i][t] = 0.f;
    float lacc[4] = {0.f, 0.f, 0.f, 0.f};          // row-sum accumulator via MMA
    const uint32_t ones2[2] = {0x3F803F80u, 0x3F803F80u};   // bf16 1.0 pairs

    int qrow = warp * 16 + (lane & 15);

    for (int kt = 0; kt < 16; kt++) {
        int st = kt & 1;
        if (kt + 1 < 16) { loadKV(st ^ 1, kt + 1); cp_commit(); }

        float sacc[8][4];
#pragma unroll
        for (int n = 0; n < 8; n++)
#pragma unroll
            for (int t = 0; t < 4; t++) sacc[n][t] = 0.f;
#pragma unroll
        for (int k2 = 0; k2 < 8; k2++) {
            uint32_t a0[4], a1[4];
            ldmA(a0, sQ + (qrow * SKV + k2 * 32 + (lane >> 4) * 8) * 2);
            ldmA(a1, sQ + (qrow * SKV + k2 * 32 + 16 + (lane >> 4) * 8) * 2);
#pragma unroll
            for (int n = 0; n < 8; n++) {
                uint32_t bb[4];
                ldmB4(bb, sK + st * stKV +
                          ((n * 8 + (lane & 7)) * SKV + k2 * 32 + ((lane >> 3) & 3) * 8) * 2);
                mma16816(sacc[n], a0, bb);
                mma16816(sacc[n], a1, bb + 2);
            }
        }

        // ---- packed exp: pack pairs to bf16x2, then ex2.bf16x2 (log2 domain) ----
        uint32_t pa[4][4];
#pragma unroll
        for (int j = 0; j < 4; j++) {
            pa[j][0] = ex2_bf16x2(packbf(sacc[2 * j][0], sacc[2 * j][1]));
            pa[j][1] = ex2_bf16x2(packbf(sacc[2 * j][2], sacc[2 * j][3]));
            pa[j][2] = ex2_bf16x2(packbf(sacc[2 * j + 1][0], sacc[2 * j + 1][1]));
            pa[j][3] = ex2_bf16x2(packbf(sacc[2 * j + 1][2], sacc[2 * j + 1][3]));
            // row sums via MMA against ones (accumulates across j and kt)
            mma16816(lacc, pa[j], ones2);
        }

        // ---- O += P @ V ----
#pragma unroll
        for (int j = 0; j < 4; j++) {
#pragma unroll
            for (int np = 0; np < 16; np++) {
                uint32_t bb[4];
                ldmBT4(bb, sV + st * stKV +
                           ((j * 16 + (lane & 15)) * SKV + np * 16 + ((lane >> 4) & 1) * 8) * 2);
                mma16816(oacc[2 * np], pa[j], bb);
                mma16816(oacc[2 * np + 1], pa[j], bb + 2);
            }
        }

        if (kt + 1 < 16) cp_wait0();
        __syncthreads();
    }

    // lacc[0] = row sum for row (lane>>2); lacc[2] = row+8. No shuffles needed.
    float inv0 = 1.f / (lacc[0] * 16.f), inv1 = 1.f / (lacc[2] * 16.f);
    int row0 = (int)(tokBase) + qt * BR + warp * 16 + (lane >> 2);
#pragma unroll
    for (int c = 0; c < 32; c++) {
        int col = c * 8 + (lane & 3) * 2;
        *(__nv_bfloat162*)(o + (size_t)row0 * EDIM + col) =
            __floats2bfloat162_rn(oacc[c][0] * inv0, oacc[c][1] * inv0);
        *(__nv_bfloat162*)(o + (size_t)(row0 + 8) * EDIM + col) =
            __floats2bfloat162_rn(oacc[c][2] * inv1, oacc[c][3] * inv1);
    }
}

// ---------------- host launch ----------------
extern "C" void kernel_launch(void* const* d_in, const int* in_sizes, int n_in,
                              void* d_out, int out_size) {
    const float* x    = (const float*)d_in[0];
    const float* ln1w = (const float*)d_in[1];
    const float* ln1b = (const float*)d_in[2];
    const float* Wq   = (const float*)d_in[3];
    const float* bq   = (const float*)d_in[4];
    const float* Wk   = (const float*)d_in[5];
    const float* bk   = (const float*)d_in[6];
    const float* Wv   = (const float*)d_in[7];
    const float* bv   = (const float*)d_in[8];
    const float* Wp   = (const float*)d_in[9];
    const float* bp   = (const float*)d_in[10];
    const float* ln2w = (const float*)d_in[11];
    const float* ln2b = (const float*)d_in[12];
    const float* W1   = (const float*)d_in[13];
    const float* b1   = (const float*)d_in[14];
    const float* W2   = (const float*)d_in[15];
    const float* b2   = (const float*)d_in[16];
    float* out = (float*)d_out;

    bf16 *xn, *qkv, *ob, *hb, *wqkv, *wp, *w1, *w2;
    float *x1, *bqkv;
    cudaGetSymbolAddress((void**)&xn,   g_xn);
    cudaGetSymbolAddress((void**)&qkv,  g_qkv);
    cudaGetSymbolAddress((void**)&ob,   g_ob);
    cudaGetSymbolAddress((void**)&x1,   g_x1);
    cudaGetSymbolAddress((void**)&hb,   g_hb);
    cudaGetSymbolAddress((void**)&wqkv, g_wqkv);
    cudaGetSymbolAddress((void**)&wp,   g_wp);
    cudaGetSymbolAddress((void**)&w1,   g_w1);
    cudaGetSymbolAddress((void**)&w2,   g_w2);
    cudaGetSymbolAddress((void**)&bqkv, g_bqkv);

    cudaFuncSetAttribute(flash_kernel, cudaFuncAttributeMaxDynamicSharedMemorySize, FSMEM);
    cudaFuncSetAttribute(gemm_tn<0, 0, 1>, cudaFuncAttributeMaxDynamicSharedMemorySize, GSMEM);
    cudaFuncSetAttribute(gemm_tn<0, 1, 0>, cudaFuncAttributeMaxDynamicSharedMemorySize, GSMEM);
    cudaFuncSetAttribute(gemm_tn<1, 0, 1>, cudaFuncAttributeMaxDynamicSharedMemorySize, GSMEM);
    cudaFuncSetAttribute(gemm_tn<1, 1, 0>, cudaFuncAttributeMaxDynamicSharedMemorySize, GSMEM);

    cvt_all<<<3075, 256>>>(Wq, Wk, Wv, Wp, W1, W2, bq, bk, bv);
    ln_kernel<<<MROWS / 8, 256>>>(x, ln1w, ln1b, xn);
    // QKV: [M,768] = xn @ Wqkv^T + bqkv   (q section in log2 domain)
    gemm_tn<0, 0, 1><<<dim3(6, 256), 256, GSMEM>>>(xn, wqkv, bqkv, nullptr, nullptr, qkv,
                                                   MROWS, 3 * EDIM, EDIM);
    flash_kernel<<<dim3(NBH, DHEAD / BR), 256, FSMEM>>>(qkv, ob);
    // x1 = O @ Wp^T + bp + x
    gemm_tn<0, 1, 0><<<dim3(2, 256), 256, GSMEM>>>(ob, wp, bp, x, x1, nullptr,
                                                   MROWS, EDIM, EDIM);
    ln_kernel<<<MROWS / 8, 256>>>(x1, ln2w, ln2b, xn);
    // h = mish(xn @ W1^T + b1)
    gemm_tn<1, 0, 1><<<dim3(8, 256), 256, GSMEM>>>(xn, w1, b1, nullptr, nullptr, hb,
                                                   MROWS, HIDDIM, EDIM);
    // out = mish(h @ W2^T + b2) + x1
    gemm_tn<1, 1, 0><<<dim3(2, 256), 256, GSMEM>>>(hb, w2, b2, x1, out, nullptr,
                                                   MROWS, EDIM, HIDDIM);
}

// round 17
// speedup vs baseline: 1.0416x; 1.0053x over previous
#include <cuda_runtime.h>
#include <cuda_bf16.h>
#include <math.h>
#include <stdint.h>

#define EDIM 256
#define HIDDIM 1024
#define MROWS 32768          // B*N
#define DHEAD 1024           // tokens per (b,h) chunk
#define NBH 32

typedef __nv_bfloat16 bf16;

// ---------------- scratch (device globals; no allocations) ----------------
__device__ __align__(256) bf16  g_xn [MROWS * EDIM];
__device__ __align__(256) bf16  g_qkv[MROWS * 3 * EDIM];   // [row][768]: q|k|v
__device__ __align__(256) bf16  g_ob [MROWS * EDIM];
__device__ __align__(256) float g_x1 [MROWS * EDIM];
__device__ __align__(256) bf16  g_hb [MROWS * HIDDIM];
__device__ __align__(256) bf16  g_wqkv[3 * EDIM * EDIM];
__device__ __align__(256) bf16  g_wp [EDIM * EDIM];
__device__ __align__(256) bf16  g_w1 [HIDDIM * EDIM];
__device__ __align__(256) bf16  g_w2 [EDIM * HIDDIM];
__device__ __align__(256) float g_bqkv[3 * EDIM];

// ---------------- helpers ----------------
__device__ __forceinline__ uint32_t smem_u32(const void* p) {
    return (uint32_t)__cvta_generic_to_shared(p);
}
__device__ __forceinline__ void cp16(uint32_t s, const void* g) {
    asm volatile("cp.async.cg.shared.global [%0], [%1], 16;\n" :: "r"(s), "l"(g));
}
__device__ __forceinline__ void cp_commit() { asm volatile("cp.async.commit_group;\n"); }
__device__ __forceinline__ void cp_wait0()  { asm volatile("cp.async.wait_group 0;\n"); }

__device__ __forceinline__ void ldmA(uint32_t* a, uint32_t addr) {
    asm volatile("ldmatrix.sync.aligned.m8n8.x4.shared.b16 {%0,%1,%2,%3}, [%4];"
                 : "=r"(a[0]), "=r"(a[1]), "=r"(a[2]), "=r"(a[3]) : "r"(addr));
}
__device__ __forceinline__ void ldmB4(uint32_t* b, uint32_t addr) {
    asm volatile("ldmatrix.sync.aligned.m8n8.x4.shared.b16 {%0,%1,%2,%3}, [%4];"
                 : "=r"(b[0]), "=r"(b[1]), "=r"(b[2]), "=r"(b[3]) : "r"(addr));
}
__device__ __forceinline__ void ldmBT4(uint32_t* b, uint32_t addr) {
    asm volatile("ldmatrix.sync.aligned.m8n8.x4.trans.shared.b16 {%0,%1,%2,%3}, [%4];"
                 : "=r"(b[0]), "=r"(b[1]), "=r"(b[2]), "=r"(b[3]) : "r"(addr));
}
__device__ __forceinline__ void mma16816(float* c, const uint32_t* a, const uint32_t* b) {
    asm volatile("mma.sync.aligned.m16n8k16.row.col.f32.bf16.bf16.f32 "
                 "{%0,%1,%2,%3},{%4,%5,%6,%7},{%8,%9},{%0,%1,%2,%3};"
                 : "+f"(c[0]), "+f"(c[1]), "+f"(c[2]), "+f"(c[3])
                 : "r"(a[0]), "r"(a[1]), "r"(a[2]), "r"(a[3]), "r"(b[0]), "r"(b[1]));
}
__device__ __forceinline__ float mish_f(float x) {
    float sp = (x > 20.0f) ? x : __logf(1.0f + __expf(x));
    float t;
    asm("tanh.approx.f32 %0, %1;" : "=f"(t) : "f"(sp));
    return x * t;
}
__device__ __forceinline__ uint32_t packbf(float a, float b) {
    __nv_bfloat162 h = __floats2bfloat162_rn(a, b);
    return *(uint32_t*)&h;
}

// ---------------- weights fp32->bf16 + bias concat, ONE launch ----------------
__global__ void cvt_all(const float* __restrict__ Wq, const float* __restrict__ Wk,
                        const float* __restrict__ Wv, const float* __restrict__ Wp,
                        const float* __restrict__ W1, const float* __restrict__ W2,
                        const float* __restrict__ bq, const float* __restrict__ bk,
                        const float* __restrict__ bv) {
    int i = blockIdx.x * 256 + threadIdx.x;
    if (i < 65536)        g_wqkv[i] = __float2bfloat16(Wq[i]);
    else if (i < 131072)  g_wqkv[i] = __float2bfloat16(Wk[i - 65536]);
    else if (i < 196608)  g_wqkv[i] = __float2bfloat16(Wv[i - 131072]);
    else if (i < 262144)  g_wp[i - 196608] = __float2bfloat16(Wp[i - 196608]);
    else if (i < 524288)  g_w1[i - 262144] = __float2bfloat16(W1[i - 262144]);
    else if (i < 786432)  g_w2[i - 524288] = __float2bfloat16(W2[i - 524288]);
    else {
        int j = i - 786432;   // 0..767
        if (j < 768)
            g_bqkv[j] = (j < 256) ? bq[j] : (j < 512 ? bk[j - 256] : bv[j - 512]);
    }
}

// ---------------- LayerNorm (fp32 in -> bf16 out) ----------------
__global__ __launch_bounds__(256) void ln_kernel(const float* __restrict__ x,
                                                 const float* __restrict__ w,
                                                 const float* __restrict__ b,
                                                 bf16* __restrict__ y) {
    int warp = threadIdx.x >> 5, lane = threadIdx.x & 31;
    int row = blockIdx.x * 8 + warp;
    const float* xr = x + (size_t)row * EDIM;
    float v[8];
#pragma unroll
    for (int i = 0; i < 8; i++) v[i] = xr[lane + i * 32];
    float s = 0.f;
#pragma unroll
    for (int i = 0; i < 8; i++) s += v[i];
#pragma unroll
    for (int o = 16; o > 0; o >>= 1) s += __shfl_xor_sync(0xffffffffu, s, o);
    float mu = s * (1.f / 256.f);
    float vs = 0.f;
#pragma unroll
    for (int i = 0; i < 8; i++) { float d = v[i] - mu; vs += d * d; }
#pragma unroll
    for (int o = 16; o > 0; o >>= 1) vs += __shfl_xor_sync(0xffffffffu, vs, o);
    float inv = rsqrtf(vs * (1.f / 256.f) + 1e-5f);
    bf16* yr = y + (size_t)row * EDIM;
#pragma unroll
    for (int i = 0; i < 8; i++) {
        int c = lane + i * 32;
        yr[c] = __float2bfloat16((v[i] - mu) * inv * w[c] + b[c]);
    }
}

// ---------------- TN GEMM: C[M,N] = epi(A[M,K] @ B[N,K]^T + bias) ----------------
// CTA 128x128, 8 warps (2m x 4n), warp tile 64x32, BK=64, 2-stage cp.async.
#define SKA 72
#define GSMEM (2 * 2 * 128 * SKA * 2)
template <int ACT, int RES, int OUTBF>
__global__ __launch_bounds__(256) void gemm_tn(const bf16* __restrict__ A,
                                               const bf16* __restrict__ B,
                                               const float* __restrict__ bias,
                                               const float* __restrict__ res,
                                               float* __restrict__ Cf,
                                               bf16* __restrict__ Cb,
                                               int M, int N, int K) {
    extern __shared__ bf16 gsm[];
    bf16* As = gsm;                     // [2][128*SKA]
    bf16* Bs = gsm + 2 * 128 * SKA;     // [2][128*SKA]
    int tid = threadIdx.x, lane = tid & 31, warp = tid >> 5;
    int wm = warp >> 2, wn = warp & 3;
    int m0 = blockIdx.y * 128, n0 = blockIdx.x * 128;
    uint32_t sA = smem_u32(As), sB = smem_u32(Bs);
    const uint32_t stageB = 128 * SKA * 2;

    float acc[4][4][4];
#pragma unroll
    for (int i = 0; i < 4; i++)
#pragma unroll
        for (int j = 0; j < 4; j++)
#pragma unroll
            for (int t = 0; t < 4; t++) acc[i][j][t] = 0.f;

    int KT = K >> 6;

    auto load = [&](int st, int kt) {
#pragma unroll
        for (int i = 0; i < 4; i++) {
            int id = i * 256 + tid, r = id >> 3, c = id & 7;
            const bf16* ag = A + (size_t)(m0 + r) * K + kt * 64 + c * 8;
            cp16(sA + st * stageB + (r * SKA + c * 8) * 2, ag);
            const bf16* bg = B + (size_t)(n0 + r) * K + kt * 64 + c * 8;
            cp16(sB + st * stageB + (r * SKA + c * 8) * 2, bg);
        }
    };

    load(0, 0); cp_commit(); cp_wait0(); __syncthreads();
    for (int kt = 0; kt < KT; kt++) {
        int st = kt & 1;
        if (kt + 1 < KT) { load(st ^ 1, kt + 1); cp_commit(); }
        uint32_t ba = sA + st * stageB;
        uint32_t bb = sB + st * stageB;
#pragma unroll
        for (int kk = 0; kk < 4; kk++) {
            uint32_t af[4][4], bfr[4][2];
#pragma unroll
            for (int mi = 0; mi < 4; mi++) {
                int row = wm * 64 + mi * 16 + (lane & 15);
                ldmA(af[mi], ba + (row * SKA + kk * 16 + (lane >> 4) * 8) * 2);
            }
#pragma unroll
            for (int nh = 0; nh < 2; nh++) {
                uint32_t bt[4];
                int nrow = wn * 32 + nh * 16 + (lane >> 4) * 8 + (lane & 7);
                ldmB4(bt, bb + (nrow * SKA + kk * 16 + ((lane >> 3) & 1) * 8) * 2);
                bfr[nh * 2][0] = bt[0]; bfr[nh * 2][1] = bt[1];
                bfr[nh * 2 + 1][0] = bt[2]; bfr[nh * 2 + 1][1] = bt[3];
            }
#pragma unroll
            for (int mi = 0; mi < 4; mi++)
#pragma unroll
                for (int ni = 0; ni < 4; ni++) mma16816(acc[mi][ni], af[mi], bfr[ni]);
        }
        if (kt + 1 < KT) cp_wait0();
        __syncthreads();
    }

#pragma unroll
    for (int mi = 0; mi < 4; mi++) {
#pragma unroll
        for (int ni = 0; ni < 4; ni++) {
            int c0 = n0 + wn * 32 + ni * 8 + (lane & 3) * 2;
            float b0 = 0.f, b1 = 0.f;
            if (bias) { b0 = bias[c0]; b1 = bias[c0 + 1]; }
#pragma unroll
            for (int h = 0; h < 2; h++) {
                int r = m0 + wm * 64 + mi * 16 + (lane >> 2) + h * 8;
                float v0 = acc[mi][ni][h * 2 + 0] + b0;
                float v1 = acc[mi][ni][h * 2 + 1] + b1;
                if (ACT) { v0 = mish_f(v0); v1 = mish_f(v1); }
                if (RES) {
                    float2 rr = *(const float2*)(res + (size_t)r * N + c0);
                    v0 += rr.x; v1 += rr.y;
                }
                if (OUTBF)
                    *(__nv_bfloat162*)(Cb + (size_t)r * N + c0) = __floats2bfloat162_rn(v0, v1);
                else
                    *(float2*)(Cf + (size_t)r * N + c0) = make_float2(v0, v1);
            }
        }
    }
}

// ---------------- Fused flash attention: no online max (scores bounded) ----------
// grid (32 bh, 8 qtiles) x 256 threads. Br=128, Bc=64, d=256.
#define BR 128
#define BC 64
#define SKV 264
#define FSMEM ((BR * SKV + 4 * BC * SKV) * 2)

__global__ __launch_bounds__(256, 1) void flash_kernel(const bf16* __restrict__ qkv,
                                                       bf16* __restrict__ o) {
    extern __shared__ bf16 fsm[];
    bf16* Qs = fsm;
    bf16* Ks = Qs + BR * SKV;
    bf16* Vs = Ks + 2 * BC * SKV;
    int tid = threadIdx.x, lane = tid & 31, warp = tid >> 5;
    int bh = blockIdx.x, qt = blockIdx.y;
    size_t tokBase = (size_t)bh * DHEAD;
    uint32_t sQ = smem_u32(Qs), sK = smem_u32(Ks), sV = smem_u32(Vs);
    const uint32_t stKV = BC * SKV * 2;

    {
        const bf16* qg = qkv + (tokBase + (size_t)qt * BR) * 768;
#pragma unroll
        for (int i = 0; i < 16; i++) {
            int c = tid + i * 256; int r = c >> 5, c8 = c & 31;
            cp16(sQ + (r * SKV + c8 * 8) * 2, qg + (size_t)r * 768 + c8 * 8);
        }
    }
    auto loadKV = [&](int st, int kt) {
        const bf16* kg = qkv + (tokBase + (size_t)kt * BC) * 768 + 256;
#pragma unroll
        for (int i = 0; i < 8; i++) {
            int c = tid + i * 256; int r = c >> 5, c8 = c & 31;
            cp16(sK + st * stKV + (r * SKV + c8 * 8) * 2, kg + (size_t)r * 768 + c8 * 8);
            cp16(sV + st * stKV + (r * SKV + c8 * 8) * 2, kg + (size_t)r * 768 + 256 + c8 * 8);
        }
    };
    loadKV(0, 0); cp_commit(); cp_wait0(); __syncthreads();

    float oacc[32][4];
#pragma unroll
    for (int i = 0; i < 32; i++)
#pragma unroll
        for (int t = 0; t < 4; t++) oacc[i][t] = 0.f;
    float l0 = 0.f, l1 = 0.f;

    int qrow = warp * 16 + (lane & 15);

    for (int kt = 0; kt < 16; kt++) {
        int st = kt & 1;
        if (kt + 1 < 16) { loadKV(st ^ 1, kt + 1); cp_commit(); }

        float sacc[8][4];
#pragma unroll
        for (int n = 0; n < 8; n++)
#pragma unroll
            for (int t = 0; t < 4; t++) sacc[n][t] = 0.f;
#pragma unroll
        for (int k2 = 0; k2 < 8; k2++) {
            uint32_t a0[4], a1[4];
            ldmA(a0, sQ + (qrow * SKV + k2 * 32 + (lane >> 4) * 8) * 2);
            ldmA(a1, sQ + (qrow * SKV + k2 * 32 + 16 + (lane >> 4) * 8) * 2);
#pragma unroll
            for (int n = 0; n < 8; n++) {
                uint32_t bb[4];
                ldmB4(bb, sK + st * stKV +
                          ((n * 8 + (lane & 7)) * SKV + k2 * 32 + ((lane >> 3) & 3) * 8) * 2);
                mma16816(sacc[n], a0, bb);
                mma16816(sacc[n], a1, bb + 2);
            }
        }

        uint32_t pa[4][4];
#pragma unroll
        for (int j = 0; j < 4; j++) {
            float e00 = __expf(sacc[2 * j][0]), e01 = __expf(sacc[2 * j][1]);
            float e02 = __expf(sacc[2 * j][2]), e03 = __expf(sacc[2 * j][3]);
            float e10 = __expf(sacc[2 * j + 1][0]), e11 = __expf(sacc[2 * j + 1][1]);
            float e12 = __expf(sacc[2 * j + 1][2]), e13 = __expf(sacc[2 * j + 1][3]);
            l0 += e00 + e01 + e10 + e11;
            l1 += e02 + e03 + e12 + e13;
            pa[j][0] = packbf(e00, e01);
            pa[j][1] = packbf(e02, e03);
            pa[j][2] = packbf(e10, e11);
            pa[j][3] = packbf(e12, e13);
        }

#pragma unroll
        for (int j = 0; j < 4; j++) {
#pragma unroll
            for (int np = 0; np < 16; np++) {
                uint32_t bb[4];
                ldmBT4(bb, sV + st * stKV +
                           ((j * 16 + (lane & 15)) * SKV + np * 16 + ((lane >> 4) & 1) * 8) * 2);
                mma16816(oacc[2 * np], pa[j], bb);
                mma16816(oacc[2 * np + 1], pa[j], bb + 2);
            }
        }

        if (kt + 1 < 16) cp_wait0();
        __syncthreads();
    }

    l0 += __shfl_xor_sync(0xffffffffu, l0, 1);
    l0 += __shfl_xor_sync(0xffffffffu, l0, 2);
    l1 += __shfl_xor_sync(0xffffffffu, l1, 1);
    l1 += __shfl_xor_sync(0xffffffffu, l1, 2);
    float inv0 = 1.f / (l0 * 16.f), inv1 = 1.f / (l1 * 16.f);
    int row0 = (int)(tokBase) + qt * BR + warp * 16 + (lane >> 2);
#pragma unroll
    for (int c = 0; c < 32; c++) {
        int col = c * 8 + (lane & 3) * 2;
        *(__nv_bfloat162*)(o + (size_t)row0 * EDIM + col) =
            __floats2bfloat162_rn(oacc[c][0] * inv0, oacc[c][1] * inv0);
        *(__nv_bfloat162*)(o + (size_t)(row0 + 8) * EDIM + col) =
            __floats2bfloat162_rn(oacc[c][2] * inv1, oacc[c][3] * inv1);
    }
}

// ---------------- host launch ----------------
extern "C" void kernel_launch(void* const* d_in, const int* in_sizes, int n_in,
                              void* d_out, int out_size) {
    const float* x    = (const float*)d_in[0];
    const float* ln1w = (const float*)d_in[1];
    const float* ln1b = (const float*)d_in[2];
    const float* Wq   = (const float*)d_in[3];
    const float* bq   = (const float*)d_in[4];
    const float* Wk   = (const float*)d_in[5];
    const float* bk   = (const float*)d_in[6];
    const float* Wv   = (const float*)d_in[7];
    const float* bv   = (const float*)d_in[8];
    const float* Wp   = (const float*)d_in[9];
    const float* bp   = (const float*)d_in[10];
    const float* ln2w = (const float*)d_in[11];
    const float* ln2b = (const float*)d_in[12];
    const float* W1   = (const float*)d_in[13];
    const float* b1   = (const float*)d_in[14];
    const float* W2   = (const float*)d_in[15];
    const float* b2   = (const float*)d_in[16];
    float* out = (float*)d_out;

    bf16 *xn, *qkv, *ob, *hb, *wqkv, *wp, *w1, *w2;
    float *x1, *bqkv;
    cudaGetSymbolAddress((void**)&xn,   g_xn);
    cudaGetSymbolAddress((void**)&qkv,  g_qkv);
    cudaGetSymbolAddress((void**)&ob,   g_ob);
    cudaGetSymbolAddress((void**)&x1,   g_x1);
    cudaGetSymbolAddress((void**)&hb,   g_hb);
    cudaGetSymbolAddress((void**)&wqkv, g_wqkv);
    cudaGetSymbolAddress((void**)&wp,   g_wp);
    cudaGetSymbolAddress((void**)&w1,   g_w1);
    cudaGetSymbolAddress((void**)&w2,   g_w2);
    cudaGetSymbolAddress((void**)&bqkv, g_bqkv);

    cudaFuncSetAttribute(flash_kernel, cudaFuncAttributeMaxDynamicSharedMemorySize, FSMEM);
    cudaFuncSetAttribute(gemm_tn<0, 0, 1>, cudaFuncAttributeMaxDynamicSharedMemorySize, GSMEM);
    cudaFuncSetAttribute(gemm_tn<0, 1, 0>, cudaFuncAttributeMaxDynamicSharedMemorySize, GSMEM);
    cudaFuncSetAttribute(gemm_tn<1, 0, 1>, cudaFuncAttributeMaxDynamicSharedMemorySize, GSMEM);
    cudaFuncSetAttribute(gemm_tn<1, 1, 0>, cudaFuncAttributeMaxDynamicSharedMemorySize, GSMEM);

    cvt_all<<<3075, 256>>>(Wq, Wk, Wv, Wp, W1, W2, bq, bk, bv);
    ln_kernel<<<MROWS / 8, 256>>>(x, ln1w, ln1b, xn);
    // QKV: [M,768] = xn @ Wqkv^T + bqkv
    gemm_tn<0, 0, 1><<<dim3(6, 256), 256, GSMEM>>>(xn, wqkv, bqkv, nullptr, nullptr, qkv,
                                                   MROWS, 3 * EDIM, EDIM);
    flash_kernel<<<dim3(NBH, DHEAD / BR), 256, FSMEM>>>(qkv, ob);
    // x1 = O @ Wp^T + bp + x
    gemm_tn<0, 1, 0><<<dim3(2, 256), 256, GSMEM>>>(ob, wp, bp, x, x1, nullptr,
                                                   MROWS, EDIM, EDIM);
    ln_kernel<<<MROWS / 8, 256>>>(x1, ln2w, ln2b, xn);
    // h = mish(xn @ W1^T + b1)
    gemm_tn<1, 0, 1><<<dim3(8, 256), 256, GSMEM>>>(xn, w1, b1, nullptr, nullptr, hb,
                                                   MROWS, HIDDIM, EDIM);
    // out = mish(h @ W2^T + b2) + x1
    gemm_tn<1, 1, 0><<<dim3(2, 256), 256, GSMEM>>>(hb, w2, b2, x1, out, nullptr,
                                                   MROWS, EDIM, HIDDIM);
}